// round 1
// baseline (speedup 1.0000x reference)
#include <cuda_runtime.h>
#include <math.h>

#define NUM_HEADS 16
#define DHEAD 64
#define DE 128          // 2*DHEAD per head
#define DMODEL 1024
#define D2 2048
#define BB 4
#define NN 1024
#define MTOT (BB*NN)    // 4096
#define QKP 132         // smem pitch for 128-wide tiles
#define PP 68           // smem pitch for 64-wide P tiles

// Scratch (device globals; allocation APIs are forbidden)
__device__ float g_Q[(size_t)BB*NUM_HEADS*NN*DE];
__device__ float g_K[(size_t)BB*NUM_HEADS*NN*DE];
__device__ float g_V[(size_t)BB*NUM_HEADS*NN*DE];
__device__ float g_Oc[(size_t)BB*NN*D2];
__device__ float g_lam[NUM_HEADS];

// ---------------------------------------------------------------------------
// lambda[h] = exp(dot(lq1[h],lk1[h])) - exp(dot(lq2[h],lk2[h])) + 0.8
// ---------------------------------------------------------------------------
__global__ void lambda_kernel(const float* __restrict__ lq1, const float* __restrict__ lk1,
                              const float* __restrict__ lq2, const float* __restrict__ lk2) {
    int w = threadIdx.x >> 5, lane = threadIdx.x & 31;
    int base = w * 64;
    float s1 = lq1[base+lane]*lk1[base+lane] + lq1[base+32+lane]*lk1[base+32+lane];
    float s2 = lq2[base+lane]*lk2[base+lane] + lq2[base+32+lane]*lk2[base+32+lane];
    #pragma unroll
    for (int off = 16; off; off >>= 1) {
        s1 += __shfl_xor_sync(0xffffffffu, s1, off);
        s2 += __shfl_xor_sync(0xffffffffu, s2, off);
    }
    if (lane == 0) g_lam[w] = expf(s1) - expf(s2) + 0.8f;
}

// ---------------------------------------------------------------------------
// SGEMM: C[M,N] = A[M,K] @ B[N,K]^T   (both row-major, K contiguous — "NT")
// BM=BN=128, BK=16, 256 threads, 8x8 micro-tile (split 4+4 to keep smem
// float4 reads ~conflict-free).
// MODE 0: C row-major (ld = N).
// MODE 1: scatter into (B,H,N,128) layout for Q/K/V scratch.
// ---------------------------------------------------------------------------
template<int MODE>
__global__ __launch_bounds__(256) void gemm_nt(const float* __restrict__ A,
                                               const float* __restrict__ Bm,
                                               float* __restrict__ C,
                                               int M, int N, int K) {
    __shared__ float As[16][132];
    __shared__ float Bs[16][132];
    int t  = threadIdx.x;
    int tx = t & 15, ty = t >> 4;
    int row0 = blockIdx.y * 128, col0 = blockIdx.x * 128;

    float acc[8][8];
    #pragma unroll
    for (int i = 0; i < 8; i++)
        #pragma unroll
        for (int j = 0; j < 8; j++) acc[i][j] = 0.f;

    const float* Arow = A  + (size_t)row0 * K;
    const float* Brow = Bm + (size_t)col0 * K;

    for (int k0 = 0; k0 < K; k0 += 16) {
        #pragma unroll
        for (int l = 0; l < 2; l++) {
            int idx = t + l * 256;       // 0..511 -> 512 float4 per operand
            int r = idx >> 2, q = (idx & 3) << 2;
            float4 va = *(const float4*)(Arow + (size_t)r * K + k0 + q);
            As[q+0][r] = va.x; As[q+1][r] = va.y; As[q+2][r] = va.z; As[q+3][r] = va.w;
            float4 vb = *(const float4*)(Brow + (size_t)r * K + k0 + q);
            Bs[q+0][r] = vb.x; Bs[q+1][r] = vb.y; Bs[q+2][r] = vb.z; Bs[q+3][r] = vb.w;
        }
        __syncthreads();
        #pragma unroll
        for (int kk = 0; kk < 16; kk++) {
            float a[8], b[8];
            *(float4*)&a[0] = *(const float4*)&As[kk][ty*4];
            *(float4*)&a[4] = *(const float4*)&As[kk][64 + ty*4];
            *(float4*)&b[0] = *(const float4*)&Bs[kk][tx*4];
            *(float4*)&b[4] = *(const float4*)&Bs[kk][64 + tx*4];
            #pragma unroll
            for (int i = 0; i < 8; i++)
                #pragma unroll
                for (int j = 0; j < 8; j++)
                    acc[i][j] += a[i] * b[j];
        }
        __syncthreads();
    }

    #pragma unroll
    for (int i = 0; i < 8; i++) {
        int r = row0 + ((i < 4) ? (ty*4 + i) : (64 + ty*4 + (i - 4)));
        #pragma unroll
        for (int jh = 0; jh < 2; jh++) {
            int col = col0 + jh*64 + tx*4;
            float4 v = make_float4(acc[i][jh*4+0], acc[i][jh*4+1],
                                   acc[i][jh*4+2], acc[i][jh*4+3]);
            if (MODE == 0) {
                *(float4*)(C + (size_t)r * N + col) = v;
            } else {
                int bb = r >> 10, n = r & 1023;
                int h  = col >> 7, e = col & 127;
                *(float4*)(C + (((size_t)(bb*NUM_HEADS + h) * NN + n) * DE + e)) = v;
            }
        }
    }
}

// ---------------------------------------------------------------------------
// Fused dual-stream flash attention + lambda-combine + RMS norm.
// Grid: (N/64, B*H). 256 threads.
// Score role:  sy=t/16 (4 rows each), sx=t%16 (4 cols each, col=j*16+sx).
// PV role:     pr=t/4 (1 row),        pg=t%4 (8 interleaved float4 d-chunks).
// ---------------------------------------------------------------------------
__global__ __launch_bounds__(256) void attn_kernel(const float* __restrict__ rms_scale) {
    extern __shared__ float sm[];
    float* Qs  = sm;
    float* Ks  = sm + 64*QKP;
    float* Vs  = sm + 2*64*QKP;
    float* P1  = sm + 3*64*QKP;
    float* P2  = P1 + 64*PP;
    float* cr1 = P2 + 64*PP;
    float* cr2 = cr1 + 64;
    float* li1 = cr2 + 64;
    float* li2 = li1 + 64;

    int t  = threadIdx.x;
    int bh = blockIdx.y;
    int h  = bh & (NUM_HEADS - 1);
    int b  = bh >> 4;
    int qb = blockIdx.x * 64;
    const float* Qp = g_Q + (size_t)bh * NN * DE;
    const float* Kp = g_K + (size_t)bh * NN * DE;
    const float* Vp = g_V + (size_t)bh * NN * DE;

    // load Q tile (64x128)
    #pragma unroll
    for (int l = 0; l < 8; l++) {
        int c = t + l*256;
        int r = c >> 5, dq = (c & 31) * 4;
        *(float4*)&Qs[r*QKP + dq] = *(const float4*)(Qp + (size_t)(qb + r)*DE + dq);
    }

    int sy = t >> 4, sx = t & 15;
    int pr = t >> 2, pg = t & 3;

    float m1[4], l1[4], m2[4], l2[4];
    #pragma unroll
    for (int i = 0; i < 4; i++) { m1[i] = -1e30f; m2[i] = -1e30f; l1[i] = 0.f; l2[i] = 0.f; }
    float4 acc1[8], acc2[8];
    #pragma unroll
    for (int j = 0; j < 8; j++) {
        acc1[j] = make_float4(0.f,0.f,0.f,0.f);
        acc2[j] = make_float4(0.f,0.f,0.f,0.f);
    }

    float lam = g_lam[h];
    __syncthreads();

    int nkb = blockIdx.x + 1;   // causal: key blocks 0..blockIdx.x
    for (int jb = 0; jb < nkb; jb++) {
        int kb = jb * 64;
        #pragma unroll
        for (int l = 0; l < 8; l++) {
            int c = t + l*256;
            int r = c >> 5, dq = (c & 31) * 4;
            *(float4*)&Ks[r*QKP + dq] = *(const float4*)(Kp + (size_t)(kb + r)*DE + dq);
            *(float4*)&Vs[r*QKP + dq] = *(const float4*)(Vp + (size_t)(kb + r)*DE + dq);
        }
        __syncthreads();

        // ---- scores (both streams) ----
        float s1[4][4], s2[4][4];
        #pragma unroll
        for (int i = 0; i < 4; i++)
            #pragma unroll
            for (int j = 0; j < 4; j++) { s1[i][j] = 0.f; s2[i][j] = 0.f; }

        #pragma unroll 4
        for (int d0 = 0; d0 < 64; d0 += 4) {
            float4 q1[4], q2[4], k1[4], k2[4];
            #pragma unroll
            for (int i = 0; i < 4; i++) {
                q1[i] = *(const float4*)&Qs[(sy*4+i)*QKP + d0];
                q2[i] = *(const float4*)&Qs[(sy*4+i)*QKP + 64 + d0];
            }
            #pragma unroll
            for (int j = 0; j < 4; j++) {
                k1[j] = *(const float4*)&Ks[(j*16+sx)*QKP + d0];
                k2[j] = *(const float4*)&Ks[(j*16+sx)*QKP + 64 + d0];
            }
            #pragma unroll
            for (int i = 0; i < 4; i++)
                #pragma unroll
                for (int j = 0; j < 4; j++) {
                    s1[i][j] += q1[i].x*k1[j].x + q1[i].y*k1[j].y + q1[i].z*k1[j].z + q1[i].w*k1[j].w;
                    s2[i][j] += q2[i].x*k2[j].x + q2[i].y*k2[j].y + q2[i].z*k2[j].z + q2[i].w*k2[j].w;
                }
        }

        // ---- scale, mask, online softmax update ----
        #pragma unroll
        for (int i = 0; i < 4; i++) {
            int rq = qb + sy*4 + i;
            int rrow = sy*4 + i;
            float mt1 = -1e30f, mt2 = -1e30f;
            #pragma unroll
            for (int j = 0; j < 4; j++) {
                int ck = kb + j*16 + sx;
                float v1 = s1[i][j] * 0.125f;
                float v2 = s2[i][j] * 0.125f;
                if (ck > rq) { v1 = -1e30f; v2 = -1e30f; }
                s1[i][j] = v1; s2[i][j] = v2;
                mt1 = fmaxf(mt1, v1); mt2 = fmaxf(mt2, v2);
            }
            #pragma unroll
            for (int off = 8; off; off >>= 1) {
                mt1 = fmaxf(mt1, __shfl_xor_sync(0xffffffffu, mt1, off));
                mt2 = fmaxf(mt2, __shfl_xor_sync(0xffffffffu, mt2, off));
            }
            float mn1 = fmaxf(m1[i], mt1), mn2 = fmaxf(m2[i], mt2);
            float c1 = __expf(m1[i] - mn1), c2 = __expf(m2[i] - mn2);
            float ps1 = 0.f, ps2 = 0.f;
            #pragma unroll
            for (int j = 0; j < 4; j++) {
                float p1 = __expf(s1[i][j] - mn1);
                float p2 = __expf(s2[i][j] - mn2);
                P1[rrow*PP + j*16 + sx] = p1;
                P2[rrow*PP + j*16 + sx] = p2;
                ps1 += p1; ps2 += p2;
            }
            #pragma unroll
            for (int off = 8; off; off >>= 1) {
                ps1 += __shfl_xor_sync(0xffffffffu, ps1, off);
                ps2 += __shfl_xor_sync(0xffffffffu, ps2, off);
            }
            l1[i] = l1[i]*c1 + ps1;
            l2[i] = l2[i]*c2 + ps2;
            m1[i] = mn1; m2[i] = mn2;
            if (sx == 0) { cr1[rrow] = c1; cr2[rrow] = c2; }
        }
        __syncthreads();

        // ---- P @ V for both streams ----
        float c1v = cr1[pr], c2v = cr2[pr];
        #pragma unroll
        for (int j = 0; j < 8; j++) {
            acc1[j].x *= c1v; acc1[j].y *= c1v; acc1[j].z *= c1v; acc1[j].w *= c1v;
            acc2[j].x *= c2v; acc2[j].y *= c2v; acc2[j].z *= c2v; acc2[j].w *= c2v;
        }
        #pragma unroll 4
        for (int k = 0; k < 64; k++) {
            float p1 = P1[pr*PP + k], p2 = P2[pr*PP + k];
            #pragma unroll
            for (int j = 0; j < 8; j++) {
                float4 v = *(const float4*)&Vs[k*QKP + (j*4 + pg)*4];
                acc1[j].x += p1*v.x; acc1[j].y += p1*v.y; acc1[j].z += p1*v.z; acc1[j].w += p1*v.w;
                acc2[j].x += p2*v.x; acc2[j].y += p2*v.y; acc2[j].z += p2*v.z; acc2[j].w += p2*v.w;
            }
        }
        __syncthreads();
    }

    // ---- finalize: combine, RMS-norm, write Oc ----
    if (sx == 0) {
        #pragma unroll
        for (int i = 0; i < 4; i++) {
            li1[sy*4+i] = 1.0f / l1[i];
            li2[sy*4+i] = 1.0f / l2[i];
        }
    }
    __syncthreads();

    float il1 = li1[pr], il2 = li2[pr];
    float o[8][4];
    float ss = 0.f;
    #pragma unroll
    for (int j = 0; j < 8; j++) {
        o[j][0] = acc1[j].x*il1 - lam*acc2[j].x*il2;
        o[j][1] = acc1[j].y*il1 - lam*acc2[j].y*il2;
        o[j][2] = acc1[j].z*il1 - lam*acc2[j].z*il2;
        o[j][3] = acc1[j].w*il1 - lam*acc2[j].w*il2;
        ss += o[j][0]*o[j][0] + o[j][1]*o[j][1] + o[j][2]*o[j][2] + o[j][3]*o[j][3];
    }
    ss += __shfl_xor_sync(0xffffffffu, ss, 1);
    ss += __shfl_xor_sync(0xffffffffu, ss, 2);
    float sc = rsqrtf(ss * (1.0f/128.0f) + 1e-5f) * 0.2f;   // (1 - lambda_init)

    size_t obase = ((size_t)b * NN + qb + pr) * D2 + h * DE;
    #pragma unroll
    for (int j = 0; j < 8; j++) {
        int d = (j*4 + pg) * 4;
        float4 rs = *(const float4*)(rms_scale + d);
        float4 out;
        out.x = o[j][0]*sc*rs.x;
        out.y = o[j][1]*sc*rs.y;
        out.z = o[j][2]*sc*rs.z;
        out.w = o[j][3]*sc*rs.w;
        *(float4*)(g_Oc + obase + d) = out;
    }
}

// ---------------------------------------------------------------------------
// Host launcher
// ---------------------------------------------------------------------------
#define ATTN_SMEM ((3*64*QKP + 2*64*PP + 4*64) * 4)   // 137216 bytes

extern "C" void kernel_launch(void* const* d_in, const int* in_sizes, int n_in,
                              void* d_out, int out_size) {
    const float* X   = (const float*)d_in[0];
    const float* Wq  = (const float*)d_in[1];
    const float* Wk  = (const float*)d_in[2];
    const float* Wv  = (const float*)d_in[3];
    const float* Wo  = (const float*)d_in[4];
    const float* lq1 = (const float*)d_in[5];
    const float* lk1 = (const float*)d_in[6];
    const float* lq2 = (const float*)d_in[7];
    const float* lk2 = (const float*)d_in[8];
    const float* rms = (const float*)d_in[9];

    float *pQ, *pK, *pV, *pOc;
    cudaGetSymbolAddress((void**)&pQ,  g_Q);
    cudaGetSymbolAddress((void**)&pK,  g_K);
    cudaGetSymbolAddress((void**)&pV,  g_V);
    cudaGetSymbolAddress((void**)&pOc, g_Oc);

    lambda_kernel<<<1, 512>>>(lq1, lk1, lq2, lk2);

    dim3 gproj(D2/128, MTOT/128);   // (16, 32)
    gemm_nt<1><<<gproj, 256>>>(X, Wq, pQ, MTOT, D2, DMODEL);
    gemm_nt<1><<<gproj, 256>>>(X, Wk, pK, MTOT, D2, DMODEL);
    gemm_nt<1><<<gproj, 256>>>(X, Wv, pV, MTOT, D2, DMODEL);

    cudaFuncSetAttribute(attn_kernel, cudaFuncAttributeMaxDynamicSharedMemorySize, ATTN_SMEM);
    attn_kernel<<<dim3(NN/64, BB*NUM_HEADS), 256, ATTN_SMEM>>>(rms);

    dim3 gout(DMODEL/128, MTOT/128);   // (8, 32)
    gemm_nt<0><<<gout, 256>>>(pOc, Wo, (float*)d_out, MTOT, DMODEL, D2);
}

// round 2
// speedup vs baseline: 1.7618x; 1.7618x over previous
#include <cuda_runtime.h>
#include <math.h>
#include <stdint.h>

#define NUM_HEADS 16
#define DHEAD 64
#define DE 128          // 2*DHEAD per head
#define DMODEL 1024
#define D2 2048
#define BB 4
#define NN 1024
#define MTOT (BB*NN)    // 4096
#define QKP 132         // smem pitch for 128-wide tiles (attention)
#define PP 68           // smem pitch for 64-wide P tiles (attention)
#define GP 36           // smem pitch for GEMM tiles (bijective bank map)

// Scratch (device globals; allocation APIs are forbidden)
__device__ float g_Q[(size_t)BB*NUM_HEADS*NN*DE];
__device__ float g_K[(size_t)BB*NUM_HEADS*NN*DE];
__device__ float g_V[(size_t)BB*NUM_HEADS*NN*DE];
__device__ float g_Oc[(size_t)BB*NN*D2];
__device__ float g_lam[NUM_HEADS];

// ---------------------------------------------------------------------------
// lambda[h] = exp(dot(lq1[h],lk1[h])) - exp(dot(lq2[h],lk2[h])) + 0.8
// ---------------------------------------------------------------------------
__global__ void lambda_kernel(const float* __restrict__ lq1, const float* __restrict__ lk1,
                              const float* __restrict__ lq2, const float* __restrict__ lk2) {
    int w = threadIdx.x >> 5, lane = threadIdx.x & 31;
    int base = w * 64;
    float s1 = lq1[base+lane]*lk1[base+lane] + lq1[base+32+lane]*lk1[base+32+lane];
    float s2 = lq2[base+lane]*lk2[base+lane] + lq2[base+32+lane]*lk2[base+32+lane];
    #pragma unroll
    for (int off = 16; off; off >>= 1) {
        s1 += __shfl_xor_sync(0xffffffffu, s1, off);
        s2 += __shfl_xor_sync(0xffffffffu, s2, off);
    }
    if (lane == 0) g_lam[w] = expf(s1) - expf(s2) + 0.8f;
}

// ---------------------------------------------------------------------------
// tf32 tensor-core GEMM: C[M,N] = A[M,K] @ W[N,K]^T   (NT, both row-major)
// 128x128x32 block tile, 256 threads = 8 warps of 64(M)x32(N).
// mma.sync.aligned.m16n8k8.row.col.f32.tf32.tf32.f32
// MODE 0: C row-major with ld = DMODEL (output projection).
// MODE 1: fused QKV; blockIdx.x selects Wq/Wk/Wv and scatters into
//         (B,H,N,128) scratch layout.
// ---------------------------------------------------------------------------
__device__ __forceinline__ uint32_t f2tf(float f) {
    uint32_t u;
    asm("cvt.rna.tf32.f32 %0, %1;" : "=r"(u) : "f"(f));
    return u;
}

__device__ __forceinline__ void mma_tf32(float* d, const uint32_t* a, const uint32_t* b) {
    asm volatile(
        "mma.sync.aligned.m16n8k8.row.col.f32.tf32.tf32.f32 "
        "{%0,%1,%2,%3}, {%4,%5,%6,%7}, {%8,%9}, {%0,%1,%2,%3};"
        : "+f"(d[0]), "+f"(d[1]), "+f"(d[2]), "+f"(d[3])
        : "r"(a[0]), "r"(a[1]), "r"(a[2]), "r"(a[3]), "r"(b[0]), "r"(b[1]));
}

template<int MODE>
__global__ __launch_bounds__(256, 2) void gemm_tf32(
    const float* __restrict__ A,
    const float* __restrict__ B0, const float* __restrict__ B1, const float* __restrict__ B2,
    float* __restrict__ C0, float* __restrict__ C1, float* __restrict__ C2,
    int K)
{
    __shared__ float As[128][GP];
    __shared__ float Bs[128][GP];

    int t = threadIdx.x;
    int wid = t >> 5, lane = t & 31;
    int row0 = blockIdx.y * 128;

    const float* Bm;
    float* C;
    int col0;
    if (MODE == 1) {
        int which = blockIdx.x >> 4;
        col0 = (blockIdx.x & 15) * 128;
        Bm = (which == 0) ? B0 : ((which == 1) ? B1 : B2);
        C  = (which == 0) ? C0 : ((which == 1) ? C1 : C2);
    } else {
        col0 = blockIdx.x * 128;
        Bm = B0; C = C0;
    }

    // global staging: 4 float4 rows per thread per operand
    int r0 = t >> 3;              // 0..31 (rows step by 32 via l)
    int kq = (t & 7) * 4;         // k offset within tile (0..28)
    const float* Ag = A  + (size_t)(row0 + r0) * K + kq;
    const float* Bg = Bm + (size_t)(col0 + r0) * K + kq;

    float4 ar[4], br[4];
    #pragma unroll
    for (int l = 0; l < 4; l++) {
        ar[l] = *(const float4*)(Ag + (size_t)l * 32 * K);
        br[l] = *(const float4*)(Bg + (size_t)l * 32 * K);
    }

    float acc[4][4][4];
    #pragma unroll
    for (int i = 0; i < 4; i++)
        #pragma unroll
        for (int j = 0; j < 4; j++)
            #pragma unroll
            for (int r = 0; r < 4; r++) acc[i][j][r] = 0.f;

    int wm = (wid & 1) * 64;      // warp M offset
    int wn = (wid >> 1) * 32;     // warp N offset
    int fr = lane >> 2;           // fragment row/col group (0..7)
    int fc = lane & 3;            // fragment k (0..3)

    for (int k0 = 0; k0 < K; k0 += 32) {
        // cvt to tf32 (RNA) and store tile to smem
        #pragma unroll
        for (int l = 0; l < 4; l++) {
            uint4 ua = make_uint4(f2tf(ar[l].x), f2tf(ar[l].y), f2tf(ar[l].z), f2tf(ar[l].w));
            *(uint4*)&As[r0 + l*32][kq] = ua;
            uint4 ub = make_uint4(f2tf(br[l].x), f2tf(br[l].y), f2tf(br[l].z), f2tf(br[l].w));
            *(uint4*)&Bs[r0 + l*32][kq] = ub;
        }
        __syncthreads();

        // prefetch next k-tile into registers
        if (k0 + 32 < K) {
            #pragma unroll
            for (int l = 0; l < 4; l++) {
                ar[l] = *(const float4*)(Ag + (size_t)l * 32 * K + k0 + 32);
                br[l] = *(const float4*)(Bg + (size_t)l * 32 * K + k0 + 32);
            }
        }

        // 4 k-chunks of 8
        #pragma unroll
        for (int kc = 0; kc < 32; kc += 8) {
            uint32_t af[4][4], bf[4][2];
            #pragma unroll
            for (int i = 0; i < 4; i++) {
                af[i][0] = __float_as_uint(As[wm + i*16 +     fr][kc +     fc]);
                af[i][1] = __float_as_uint(As[wm + i*16 + 8 + fr][kc +     fc]);
                af[i][2] = __float_as_uint(As[wm + i*16 +     fr][kc + 4 + fc]);
                af[i][3] = __float_as_uint(As[wm + i*16 + 8 + fr][kc + 4 + fc]);
            }
            #pragma unroll
            for (int j = 0; j < 4; j++) {
                bf[j][0] = __float_as_uint(Bs[wn + j*8 + fr][kc +     fc]);
                bf[j][1] = __float_as_uint(Bs[wn + j*8 + fr][kc + 4 + fc]);
            }
            #pragma unroll
            for (int i = 0; i < 4; i++)
                #pragma unroll
                for (int j = 0; j < 4; j++)
                    mma_tf32(acc[i][j], af[i], bf[j]);
        }
        __syncthreads();
    }

    // epilogue
    #pragma unroll
    for (int i = 0; i < 4; i++) {
        int rr = row0 + wm + i*16 + fr;
        #pragma unroll
        for (int j = 0; j < 4; j++) {
            int cc = col0 + wn + j*8 + fc*2;
            float2 v0 = make_float2(acc[i][j][0], acc[i][j][1]);
            float2 v1 = make_float2(acc[i][j][2], acc[i][j][3]);
            if (MODE == 0) {
                *(float2*)(C + (size_t)rr * DMODEL + cc) = v0;
                *(float2*)(C + (size_t)(rr + 8) * DMODEL + cc) = v1;
            } else {
                int h = cc >> 7, e = cc & 127;
                int bb = rr >> 10, n = rr & 1023;
                *(float2*)(C + (((size_t)(bb*NUM_HEADS + h) * NN + n) * DE + e)) = v0;
                int rr2 = rr + 8;
                bb = rr2 >> 10; n = rr2 & 1023;
                *(float2*)(C + (((size_t)(bb*NUM_HEADS + h) * NN + n) * DE + e)) = v1;
            }
        }
    }
}

// ---------------------------------------------------------------------------
// Fused dual-stream flash attention + lambda-combine + RMS norm (fp32 SIMT).
// Grid: (N/64, B*H). 256 threads.
// ---------------------------------------------------------------------------
__global__ __launch_bounds__(256) void attn_kernel(const float* __restrict__ rms_scale) {
    extern __shared__ float sm[];
    float* Qs  = sm;
    float* Ks  = sm + 64*QKP;
    float* Vs  = sm + 2*64*QKP;
    float* P1  = sm + 3*64*QKP;
    float* P2  = P1 + 64*PP;
    float* cr1 = P2 + 64*PP;
    float* cr2 = cr1 + 64;
    float* li1 = cr2 + 64;
    float* li2 = li1 + 64;

    int t  = threadIdx.x;
    int bh = blockIdx.y;
    int h  = bh & (NUM_HEADS - 1);
    int b  = bh >> 4;
    int qb = blockIdx.x * 64;
    const float* Qp = g_Q + (size_t)bh * NN * DE;
    const float* Kp = g_K + (size_t)bh * NN * DE;
    const float* Vp = g_V + (size_t)bh * NN * DE;

    #pragma unroll
    for (int l = 0; l < 8; l++) {
        int c = t + l*256;
        int r = c >> 5, dq = (c & 31) * 4;
        *(float4*)&Qs[r*QKP + dq] = *(const float4*)(Qp + (size_t)(qb + r)*DE + dq);
    }

    int sy = t >> 4, sx = t & 15;
    int pr = t >> 2, pg = t & 3;

    float m1[4], l1[4], m2[4], l2[4];
    #pragma unroll
    for (int i = 0; i < 4; i++) { m1[i] = -1e30f; m2[i] = -1e30f; l1[i] = 0.f; l2[i] = 0.f; }
    float4 acc1[8], acc2[8];
    #pragma unroll
    for (int j = 0; j < 8; j++) {
        acc1[j] = make_float4(0.f,0.f,0.f,0.f);
        acc2[j] = make_float4(0.f,0.f,0.f,0.f);
    }

    float lam = g_lam[h];
    __syncthreads();

    int nkb = blockIdx.x + 1;
    for (int jb = 0; jb < nkb; jb++) {
        int kb = jb * 64;
        #pragma unroll
        for (int l = 0; l < 8; l++) {
            int c = t + l*256;
            int r = c >> 5, dq = (c & 31) * 4;
            *(float4*)&Ks[r*QKP + dq] = *(const float4*)(Kp + (size_t)(kb + r)*DE + dq);
            *(float4*)&Vs[r*QKP + dq] = *(const float4*)(Vp + (size_t)(kb + r)*DE + dq);
        }
        __syncthreads();

        float s1[4][4], s2[4][4];
        #pragma unroll
        for (int i = 0; i < 4; i++)
            #pragma unroll
            for (int j = 0; j < 4; j++) { s1[i][j] = 0.f; s2[i][j] = 0.f; }

        #pragma unroll 4
        for (int d0 = 0; d0 < 64; d0 += 4) {
            float4 q1[4], q2[4], k1[4], k2[4];
            #pragma unroll
            for (int i = 0; i < 4; i++) {
                q1[i] = *(const float4*)&Qs[(sy*4+i)*QKP + d0];
                q2[i] = *(const float4*)&Qs[(sy*4+i)*QKP + 64 + d0];
            }
            #pragma unroll
            for (int j = 0; j < 4; j++) {
                k1[j] = *(const float4*)&Ks[(j*16+sx)*QKP + d0];
                k2[j] = *(const float4*)&Ks[(j*16+sx)*QKP + 64 + d0];
            }
            #pragma unroll
            for (int i = 0; i < 4; i++)
                #pragma unroll
                for (int j = 0; j < 4; j++) {
                    s1[i][j] += q1[i].x*k1[j].x + q1[i].y*k1[j].y + q1[i].z*k1[j].z + q1[i].w*k1[j].w;
                    s2[i][j] += q2[i].x*k2[j].x + q2[i].y*k2[j].y + q2[i].z*k2[j].z + q2[i].w*k2[j].w;
                }
        }

        #pragma unroll
        for (int i = 0; i < 4; i++) {
            int rq = qb + sy*4 + i;
            int rrow = sy*4 + i;
            float mt1 = -1e30f, mt2 = -1e30f;
            #pragma unroll
            for (int j = 0; j < 4; j++) {
                int ck = kb + j*16 + sx;
                float v1 = s1[i][j] * 0.125f;
                float v2 = s2[i][j] * 0.125f;
                if (ck > rq) { v1 = -1e30f; v2 = -1e30f; }
                s1[i][j] = v1; s2[i][j] = v2;
                mt1 = fmaxf(mt1, v1); mt2 = fmaxf(mt2, v2);
            }
            #pragma unroll
            for (int off = 8; off; off >>= 1) {
                mt1 = fmaxf(mt1, __shfl_xor_sync(0xffffffffu, mt1, off));
                mt2 = fmaxf(mt2, __shfl_xor_sync(0xffffffffu, mt2, off));
            }
            float mn1 = fmaxf(m1[i], mt1), mn2 = fmaxf(m2[i], mt2);
            float c1 = __expf(m1[i] - mn1), c2 = __expf(m2[i] - mn2);
            float ps1 = 0.f, ps2 = 0.f;
            #pragma unroll
            for (int j = 0; j < 4; j++) {
                float p1 = __expf(s1[i][j] - mn1);
                float p2 = __expf(s2[i][j] - mn2);
                P1[rrow*PP + j*16 + sx] = p1;
                P2[rrow*PP + j*16 + sx] = p2;
                ps1 += p1; ps2 += p2;
            }
            #pragma unroll
            for (int off = 8; off; off >>= 1) {
                ps1 += __shfl_xor_sync(0xffffffffu, ps1, off);
                ps2 += __shfl_xor_sync(0xffffffffu, ps2, off);
            }
            l1[i] = l1[i]*c1 + ps1;
            l2[i] = l2[i]*c2 + ps2;
            m1[i] = mn1; m2[i] = mn2;
            if (sx == 0) { cr1[rrow] = c1; cr2[rrow] = c2; }
        }
        __syncthreads();

        float c1v = cr1[pr], c2v = cr2[pr];
        #pragma unroll
        for (int j = 0; j < 8; j++) {
            acc1[j].x *= c1v; acc1[j].y *= c1v; acc1[j].z *= c1v; acc1[j].w *= c1v;
            acc2[j].x *= c2v; acc2[j].y *= c2v; acc2[j].z *= c2v; acc2[j].w *= c2v;
        }
        #pragma unroll 4
        for (int k = 0; k < 64; k++) {
            float p1 = P1[pr*PP + k], p2 = P2[pr*PP + k];
            #pragma unroll
            for (int j = 0; j < 8; j++) {
                float4 v = *(const float4*)&Vs[k*QKP + (j*4 + pg)*4];
                acc1[j].x += p1*v.x; acc1[j].y += p1*v.y; acc1[j].z += p1*v.z; acc1[j].w += p1*v.w;
                acc2[j].x += p2*v.x; acc2[j].y += p2*v.y; acc2[j].z += p2*v.z; acc2[j].w += p2*v.w;
            }
        }
        __syncthreads();
    }

    if (sx == 0) {
        #pragma unroll
        for (int i = 0; i < 4; i++) {
            li1[sy*4+i] = 1.0f / l1[i];
            li2[sy*4+i] = 1.0f / l2[i];
        }
    }
    __syncthreads();

    float il1 = li1[pr], il2 = li2[pr];
    float o[8][4];
    float ss = 0.f;
    #pragma unroll
    for (int j = 0; j < 8; j++) {
        o[j][0] = acc1[j].x*il1 - lam*acc2[j].x*il2;
        o[j][1] = acc1[j].y*il1 - lam*acc2[j].y*il2;
        o[j][2] = acc1[j].z*il1 - lam*acc2[j].z*il2;
        o[j][3] = acc1[j].w*il1 - lam*acc2[j].w*il2;
        ss += o[j][0]*o[j][0] + o[j][1]*o[j][1] + o[j][2]*o[j][2] + o[j][3]*o[j][3];
    }
    ss += __shfl_xor_sync(0xffffffffu, ss, 1);
    ss += __shfl_xor_sync(0xffffffffu, ss, 2);
    float sc = rsqrtf(ss * (1.0f/128.0f) + 1e-5f) * 0.2f;

    size_t obase = ((size_t)b * NN + qb + pr) * D2 + h * DE;
    #pragma unroll
    for (int j = 0; j < 8; j++) {
        int d = (j*4 + pg) * 4;
        float4 rs = *(const float4*)(rms_scale + d);
        float4 out;
        out.x = o[j][0]*sc*rs.x;
        out.y = o[j][1]*sc*rs.y;
        out.z = o[j][2]*sc*rs.z;
        out.w = o[j][3]*sc*rs.w;
        *(float4*)(g_Oc + obase + d) = out;
    }
}

// ---------------------------------------------------------------------------
// Host launcher
// ---------------------------------------------------------------------------
#define ATTN_SMEM ((3*64*QKP + 2*64*PP + 4*64) * 4)

extern "C" void kernel_launch(void* const* d_in, const int* in_sizes, int n_in,
                              void* d_out, int out_size) {
    const float* X   = (const float*)d_in[0];
    const float* Wq  = (const float*)d_in[1];
    const float* Wk  = (const float*)d_in[2];
    const float* Wv  = (const float*)d_in[3];
    const float* Wo  = (const float*)d_in[4];
    const float* lq1 = (const float*)d_in[5];
    const float* lk1 = (const float*)d_in[6];
    const float* lq2 = (const float*)d_in[7];
    const float* lk2 = (const float*)d_in[8];
    const float* rms = (const float*)d_in[9];

    float *pQ, *pK, *pV, *pOc;
    cudaGetSymbolAddress((void**)&pQ,  g_Q);
    cudaGetSymbolAddress((void**)&pK,  g_K);
    cudaGetSymbolAddress((void**)&pV,  g_V);
    cudaGetSymbolAddress((void**)&pOc, g_Oc);

    lambda_kernel<<<1, 512>>>(lq1, lk1, lq2, lk2);

    // fused QKV projection: grid.x = 3 * (2048/128) = 48 column blocks
    dim3 gqkv(48, MTOT/128);
    gemm_tf32<1><<<gqkv, 256>>>(X, Wq, Wk, Wv, pQ, pK, pV, DMODEL);

    cudaFuncSetAttribute(attn_kernel, cudaFuncAttributeMaxDynamicSharedMemorySize, ATTN_SMEM);
    attn_kernel<<<dim3(NN/64, BB*NUM_HEADS), 256, ATTN_SMEM>>>(rms);

    // output projection: C[4096,1024] = Oc[4096,2048] @ Wo[1024,2048]^T
    dim3 gout(DMODEL/128, MTOT/128);
    gemm_tf32<0><<<gout, 256>>>(pOc, Wo, nullptr, nullptr, (float*)d_out, nullptr, nullptr, D2);
}

// round 5
// speedup vs baseline: 2.5917x; 1.4710x over previous
#include <cuda_runtime.h>
#include <math.h>
#include <stdint.h>

#define NUM_HEADS 16
#define DHEAD 64
#define DE 128          // 2*DHEAD per head
#define DMODEL 1024
#define D2 2048
#define BB 4
#define NN 1024
#define MTOT (BB*NN)    // 4096
#define QKP 132         // smem pitch for Q/K tiles (score phase float4 reads)
#define VP  136         // smem pitch for V tile (conflict-free mma B-frag loads)
#define PP  68          // smem pitch for P tiles (conflict-free mma A-frag loads)
#define GP 36           // smem pitch for GEMM tiles

// Scratch (device globals; allocation APIs are forbidden)
__device__ float g_Q[(size_t)BB*NUM_HEADS*NN*DE];
__device__ float g_K[(size_t)BB*NUM_HEADS*NN*DE];
__device__ float g_V[(size_t)BB*NUM_HEADS*NN*DE];
__device__ float g_Oc[(size_t)BB*NN*D2];
__device__ float g_lam[NUM_HEADS];

__device__ __forceinline__ uint32_t f2tf(float f) {
    uint32_t u;
    asm("cvt.rna.tf32.f32 %0, %1;" : "=r"(u) : "f"(f));
    return u;
}

__device__ __forceinline__ void mma_tf32(float* d, const uint32_t* a, const uint32_t* b) {
    asm volatile(
        "mma.sync.aligned.m16n8k8.row.col.f32.tf32.tf32.f32 "
        "{%0,%1,%2,%3}, {%4,%5,%6,%7}, {%8,%9}, {%0,%1,%2,%3};"
        : "+f"(d[0]), "+f"(d[1]), "+f"(d[2]), "+f"(d[3])
        : "r"(a[0]), "r"(a[1]), "r"(a[2]), "r"(a[3]), "r"(b[0]), "r"(b[1]));
}

// ---------------------------------------------------------------------------
// lambda[h]
// ---------------------------------------------------------------------------
__global__ void lambda_kernel(const float* __restrict__ lq1, const float* __restrict__ lk1,
                              const float* __restrict__ lq2, const float* __restrict__ lk2) {
    int w = threadIdx.x >> 5, lane = threadIdx.x & 31;
    int base = w * 64;
    float s1 = lq1[base+lane]*lk1[base+lane] + lq1[base+32+lane]*lk1[base+32+lane];
    float s2 = lq2[base+lane]*lk2[base+lane] + lq2[base+32+lane]*lk2[base+32+lane];
    #pragma unroll
    for (int off = 16; off; off >>= 1) {
        s1 += __shfl_xor_sync(0xffffffffu, s1, off);
        s2 += __shfl_xor_sync(0xffffffffu, s2, off);
    }
    if (lane == 0) g_lam[w] = expf(s1) - expf(s2) + 0.8f;
}

// ---------------------------------------------------------------------------
// tf32 tensor-core GEMM: C[M,N] = A[M,K] @ W[N,K]^T   (NT, both row-major)
// 128x128x32 block tile, 256 threads = 8 warps of 64(M)x32(N).
// MODE 0: C row-major (ld = DMODEL). MODE 1: fused QKV scatter.
// ---------------------------------------------------------------------------
template<int MODE>
__global__ __launch_bounds__(256, 2) void gemm_tf32(
    const float* __restrict__ A,
    const float* __restrict__ B0, const float* __restrict__ B1, const float* __restrict__ B2,
    float* __restrict__ C0, float* __restrict__ C1, float* __restrict__ C2,
    int K)
{
    __shared__ float As[128][GP];
    __shared__ float Bs[128][GP];

    int t = threadIdx.x;
    int wid = t >> 5, lane = t & 31;
    int row0 = blockIdx.y * 128;

    const float* Bm;
    float* C;
    int col0;
    if (MODE == 1) {
        int which = blockIdx.x >> 4;
        col0 = (blockIdx.x & 15) * 128;
        Bm = (which == 0) ? B0 : ((which == 1) ? B1 : B2);
        C  = (which == 0) ? C0 : ((which == 1) ? C1 : C2);
    } else {
        col0 = blockIdx.x * 128;
        Bm = B0; C = C0;
    }

    int r0 = t >> 3;
    int kq = (t & 7) * 4;
    const float* Ag = A  + (size_t)(row0 + r0) * K + kq;
    const float* Bg = Bm + (size_t)(col0 + r0) * K + kq;

    float4 ar[4], br[4];
    #pragma unroll
    for (int l = 0; l < 4; l++) {
        ar[l] = *(const float4*)(Ag + (size_t)l * 32 * K);
        br[l] = *(const float4*)(Bg + (size_t)l * 32 * K);
    }

    float acc[4][4][4];
    #pragma unroll
    for (int i = 0; i < 4; i++)
        #pragma unroll
        for (int j = 0; j < 4; j++)
            #pragma unroll
            for (int r = 0; r < 4; r++) acc[i][j][r] = 0.f;

    int wm = (wid & 1) * 64;
    int wn = (wid >> 1) * 32;
    int fr = lane >> 2;
    int fc = lane & 3;

    for (int k0 = 0; k0 < K; k0 += 32) {
        #pragma unroll
        for (int l = 0; l < 4; l++) {
            uint4 ua = make_uint4(f2tf(ar[l].x), f2tf(ar[l].y), f2tf(ar[l].z), f2tf(ar[l].w));
            *(uint4*)&As[r0 + l*32][kq] = ua;
            uint4 ub = make_uint4(f2tf(br[l].x), f2tf(br[l].y), f2tf(br[l].z), f2tf(br[l].w));
            *(uint4*)&Bs[r0 + l*32][kq] = ub;
        }
        __syncthreads();

        if (k0 + 32 < K) {
            #pragma unroll
            for (int l = 0; l < 4; l++) {
                ar[l] = *(const float4*)(Ag + (size_t)l * 32 * K + k0 + 32);
                br[l] = *(const float4*)(Bg + (size_t)l * 32 * K + k0 + 32);
            }
        }

        #pragma unroll
        for (int kc = 0; kc < 32; kc += 8) {
            uint32_t af[4][4], bf[4][2];
            #pragma unroll
            for (int i = 0; i < 4; i++) {
                af[i][0] = __float_as_uint(As[wm + i*16 +     fr][kc +     fc]);
                af[i][1] = __float_as_uint(As[wm + i*16 + 8 + fr][kc +     fc]);
                af[i][2] = __float_as_uint(As[wm + i*16 +     fr][kc + 4 + fc]);
                af[i][3] = __float_as_uint(As[wm + i*16 + 8 + fr][kc + 4 + fc]);
            }
            #pragma unroll
            for (int j = 0; j < 4; j++) {
                bf[j][0] = __float_as_uint(Bs[wn + j*8 + fr][kc +     fc]);
                bf[j][1] = __float_as_uint(Bs[wn + j*8 + fr][kc + 4 + fc]);
            }
            #pragma unroll
            for (int i = 0; i < 4; i++)
                #pragma unroll
                for (int j = 0; j < 4; j++)
                    mma_tf32(acc[i][j], af[i], bf[j]);
        }
        __syncthreads();
    }

    #pragma unroll
    for (int i = 0; i < 4; i++) {
        int rr = row0 + wm + i*16 + fr;
        #pragma unroll
        for (int j = 0; j < 4; j++) {
            int cc = col0 + wn + j*8 + fc*2;
            float2 v0 = make_float2(acc[i][j][0], acc[i][j][1]);
            float2 v1 = make_float2(acc[i][j][2], acc[i][j][3]);
            if (MODE == 0) {
                *(float2*)(C + (size_t)rr * DMODEL + cc) = v0;
                *(float2*)(C + (size_t)(rr + 8) * DMODEL + cc) = v1;
            } else {
                int h = cc >> 7, e = cc & 127;
                int bb = rr >> 10, n = rr & 1023;
                *(float2*)(C + (((size_t)(bb*NUM_HEADS + h) * NN + n) * DE + e)) = v0;
                int rr2 = rr + 8;
                bb = rr2 >> 10; n = rr2 & 1023;
                *(float2*)(C + (((size_t)(bb*NUM_HEADS + h) * NN + n) * DE + e)) = v1;
            }
        }
    }
}

// ---------------------------------------------------------------------------
// Fused dual-stream flash attention: SIMT fp32 logits + tf32 tensor-core P@V,
// lambda-combine + RMS norm epilogue.
// Grid: (N/64, B*H). 256 threads = 8 warps.
// ---------------------------------------------------------------------------
__global__ __launch_bounds__(256) void attn_kernel(const float* __restrict__ rms_scale) {
    extern __shared__ float sm[];
    float* Qs  = sm;                       // 64 x QKP
    float* Ks  = Qs + 64*QKP;              // 64 x QKP
    float* Vs  = Ks + 64*QKP;              // 64 x VP (tf32 values)
    float* P1  = Vs + 64*VP;               // 64 x PP (tf32 values)
    float* P2  = P1 + 64*PP;
    float* cr1 = P2 + 64*PP;               // rescale factors / reused for rms
    float* cr2 = cr1 + 64;
    float* li1 = cr2 + 64;
    float* li2 = li1 + 64;

    int t  = threadIdx.x;
    int bh = blockIdx.y;
    int h  = bh & (NUM_HEADS - 1);
    int b  = bh >> 4;
    int qb = blockIdx.x * 64;
    const float* Qp = g_Q + (size_t)bh * NN * DE;
    const float* Kp = g_K + (size_t)bh * NN * DE;
    const float* Vp = g_V + (size_t)bh * NN * DE;

    // load Q tile (64x128)
    #pragma unroll
    for (int l = 0; l < 8; l++) {
        int c = t + l*256;
        int r = c >> 5, dq = (c & 31) * 4;
        *(float4*)&Qs[r*QKP + dq] = *(const float4*)(Qp + (size_t)(qb + r)*DE + dq);
    }

    // score role
    int sy = t >> 4, sx = t & 15;
    // PV role
    int lane = t & 31;
    int gid = lane >> 2, tig = lane & 3;
    int wid = t >> 5;
    int rt = (wid >> 1) * 16;      // row-tile base
    int nh = (wid & 1) * 64;       // col half

    float m1[4], l1[4], m2[4], l2[4];
    #pragma unroll
    for (int i = 0; i < 4; i++) { m1[i] = -1e30f; m2[i] = -1e30f; l1[i] = 0.f; l2[i] = 0.f; }

    float o1[8][4], o2[8][4];
    #pragma unroll
    for (int f = 0; f < 8; f++)
        #pragma unroll
        for (int r = 0; r < 4; r++) { o1[f][r] = 0.f; o2[f][r] = 0.f; }

    float lam = g_lam[h];
    __syncthreads();

    int nkb = blockIdx.x + 1;   // causal: key blocks 0..blockIdx.x
    for (int jb = 0; jb < nkb; jb++) {
        int kb = jb * 64;
        // load K (fp32) and V (tf32-rounded) tiles
        #pragma unroll
        for (int l = 0; l < 8; l++) {
            int c = t + l*256;
            int r = c >> 5, dq = (c & 31) * 4;
            *(float4*)&Ks[r*QKP + dq] = *(const float4*)(Kp + (size_t)(kb + r)*DE + dq);
            float4 vv = *(const float4*)(Vp + (size_t)(kb + r)*DE + dq);
            uint4 uv = make_uint4(f2tf(vv.x), f2tf(vv.y), f2tf(vv.z), f2tf(vv.w));
            *(uint4*)&Vs[r*VP + dq] = uv;
        }
        __syncthreads();

        // ---- logits (fp32 SIMT, both streams) ----
        float s1[4][4], s2[4][4];
        #pragma unroll
        for (int i = 0; i < 4; i++)
            #pragma unroll
            for (int j = 0; j < 4; j++) { s1[i][j] = 0.f; s2[i][j] = 0.f; }

        #pragma unroll 4
        for (int d0 = 0; d0 < 64; d0 += 4) {
            float4 q1[4], q2[4], k1[4], k2[4];
            #pragma unroll
            for (int i = 0; i < 4; i++) {
                q1[i] = *(const float4*)&Qs[(sy*4+i)*QKP + d0];
                q2[i] = *(const float4*)&Qs[(sy*4+i)*QKP + 64 + d0];
            }
            #pragma unroll
            for (int j = 0; j < 4; j++) {
                k1[j] = *(const float4*)&Ks[(j*16+sx)*QKP + d0];
                k2[j] = *(const float4*)&Ks[(j*16+sx)*QKP + 64 + d0];
            }
            #pragma unroll
            for (int i = 0; i < 4; i++)
                #pragma unroll
                for (int j = 0; j < 4; j++) {
                    s1[i][j] += q1[i].x*k1[j].x + q1[i].y*k1[j].y + q1[i].z*k1[j].z + q1[i].w*k1[j].w;
                    s2[i][j] += q2[i].x*k2[j].x + q2[i].y*k2[j].y + q2[i].z*k2[j].z + q2[i].w*k2[j].w;
                }
        }

        // ---- scale, mask, online softmax; write tf32 P ----
        #pragma unroll
        for (int i = 0; i < 4; i++) {
            int rq = qb + sy*4 + i;
            int rrow = sy*4 + i;
            float mt1 = -1e30f, mt2 = -1e30f;
            #pragma unroll
            for (int j = 0; j < 4; j++) {
                int ck = kb + j*16 + sx;
                float v1 = s1[i][j] * 0.125f;
                float v2 = s2[i][j] * 0.125f;
                if (ck > rq) { v1 = -1e30f; v2 = -1e30f; }
                s1[i][j] = v1; s2[i][j] = v2;
                mt1 = fmaxf(mt1, v1); mt2 = fmaxf(mt2, v2);
            }
            #pragma unroll
            for (int off = 8; off; off >>= 1) {
                mt1 = fmaxf(mt1, __shfl_xor_sync(0xffffffffu, mt1, off));
                mt2 = fmaxf(mt2, __shfl_xor_sync(0xffffffffu, mt2, off));
            }
            float mn1 = fmaxf(m1[i], mt1), mn2 = fmaxf(m2[i], mt2);
            float c1 = __expf(m1[i] - mn1), c2 = __expf(m2[i] - mn2);
            float ps1 = 0.f, ps2 = 0.f;
            #pragma unroll
            for (int j = 0; j < 4; j++) {
                float p1 = __uint_as_float(f2tf(__expf(s1[i][j] - mn1)));
                float p2 = __uint_as_float(f2tf(__expf(s2[i][j] - mn2)));
                P1[rrow*PP + j*16 + sx] = p1;
                P2[rrow*PP + j*16 + sx] = p2;
                ps1 += p1; ps2 += p2;
            }
            #pragma unroll
            for (int off = 8; off; off >>= 1) {
                ps1 += __shfl_xor_sync(0xffffffffu, ps1, off);
                ps2 += __shfl_xor_sync(0xffffffffu, ps2, off);
            }
            l1[i] = l1[i]*c1 + ps1;
            l2[i] = l2[i]*c2 + ps2;
            m1[i] = mn1; m2[i] = mn2;
            if (sx == 0) { cr1[rrow] = c1; cr2[rrow] = c2; }
        }
        __syncthreads();

        // ---- P @ V on tensor cores ----
        {
            float c1a = cr1[rt + gid], c1b = cr1[rt + gid + 8];
            float c2a = cr2[rt + gid], c2b = cr2[rt + gid + 8];
            #pragma unroll
            for (int f = 0; f < 8; f++) {
                o1[f][0] *= c1a; o1[f][1] *= c1a; o1[f][2] *= c1b; o1[f][3] *= c1b;
                o2[f][0] *= c2a; o2[f][1] *= c2a; o2[f][2] *= c2b; o2[f][3] *= c2b;
            }
            #pragma unroll
            for (int kc = 0; kc < 64; kc += 8) {
                uint32_t a1f[4], a2f[4];
                a1f[0] = __float_as_uint(P1[(rt+gid  )*PP + kc + tig    ]);
                a1f[1] = __float_as_uint(P1[(rt+gid+8)*PP + kc + tig    ]);
                a1f[2] = __float_as_uint(P1[(rt+gid  )*PP + kc + tig + 4]);
                a1f[3] = __float_as_uint(P1[(rt+gid+8)*PP + kc + tig + 4]);
                a2f[0] = __float_as_uint(P2[(rt+gid  )*PP + kc + tig    ]);
                a2f[1] = __float_as_uint(P2[(rt+gid+8)*PP + kc + tig    ]);
                a2f[2] = __float_as_uint(P2[(rt+gid  )*PP + kc + tig + 4]);
                a2f[3] = __float_as_uint(P2[(rt+gid+8)*PP + kc + tig + 4]);
                #pragma unroll
                for (int f = 0; f < 8; f++) {
                    uint32_t bf[2];
                    bf[0] = __float_as_uint(Vs[(kc + tig    )*VP + nh + f*8 + gid]);
                    bf[1] = __float_as_uint(Vs[(kc + tig + 4)*VP + nh + f*8 + gid]);
                    mma_tf32(o1[f], a1f, bf);
                    mma_tf32(o2[f], a2f, bf);
                }
            }
        }
        __syncthreads();
    }

    // ---- finalize ----
    if (sx == 0) {
        #pragma unroll
        for (int i = 0; i < 4; i++) {
            li1[sy*4+i] = 1.0f / l1[i];
            li2[sy*4+i] = 1.0f / l2[i];
        }
    }
    __syncthreads();

    float il1a = li1[rt + gid], il1b = li1[rt + gid + 8];
    float il2a = li2[rt + gid], il2b = li2[rt + gid + 8];

    float ssA = 0.f, ssB = 0.f;
    #pragma unroll
    for (int f = 0; f < 8; f++) {
        o1[f][0] = o1[f][0]*il1a - lam*o2[f][0]*il2a;
        o1[f][1] = o1[f][1]*il1a - lam*o2[f][1]*il2a;
        o1[f][2] = o1[f][2]*il1b - lam*o2[f][2]*il2b;
        o1[f][3] = o1[f][3]*il1b - lam*o2[f][3]*il2b;
        ssA += o1[f][0]*o1[f][0] + o1[f][1]*o1[f][1];
        ssB += o1[f][2]*o1[f][2] + o1[f][3]*o1[f][3];
    }
    ssA += __shfl_xor_sync(0xffffffffu, ssA, 1);
    ssA += __shfl_xor_sync(0xffffffffu, ssA, 2);
    ssB += __shfl_xor_sync(0xffffffffu, ssB, 1);
    ssB += __shfl_xor_sync(0xffffffffu, ssB, 2);

    // cross-warp (col-half) reduction: reuse cr1/cr2
    __syncthreads();
    if (tig == 0) {
        float* dst = (wid & 1) ? cr2 : cr1;
        dst[rt + gid]     = ssA;
        dst[rt + gid + 8] = ssB;
    }
    __syncthreads();
    float totA = cr1[rt + gid]     + cr2[rt + gid];
    float totB = cr1[rt + gid + 8] + cr2[rt + gid + 8];
    float scA = rsqrtf(totA * (1.0f/128.0f) + 1e-5f) * 0.2f;
    float scB = rsqrtf(totB * (1.0f/128.0f) + 1e-5f) * 0.2f;

    size_t obaseA = ((size_t)b * NN + qb + rt + gid)     * D2 + h * DE;
    size_t obaseB = ((size_t)b * NN + qb + rt + gid + 8) * D2 + h * DE;
    #pragma unroll
    for (int f = 0; f < 8; f++) {
        int col = nh + f*8 + 2*tig;
        float2 rs = *(const float2*)(rms_scale + col);
        *(float2*)(g_Oc + obaseA + col) = make_float2(o1[f][0]*scA*rs.x, o1[f][1]*scA*rs.y);
        *(float2*)(g_Oc + obaseB + col) = make_float2(o1[f][2]*scB*rs.x, o1[f][3]*scB*rs.y);
    }
}

// ---------------------------------------------------------------------------
// Host launcher
// ---------------------------------------------------------------------------
#define ATTN_SMEM ((2*64*QKP + 64*VP + 2*64*PP + 4*64) * 4)

extern "C" void kernel_launch(void* const* d_in, const int* in_sizes, int n_in,
                              void* d_out, int out_size) {
    const float* X   = (const float*)d_in[0];
    const float* Wq  = (const float*)d_in[1];
    const float* Wk  = (const float*)d_in[2];
    const float* Wv  = (const float*)d_in[3];
    const float* Wo  = (const float*)d_in[4];
    const float* lq1 = (const float*)d_in[5];
    const float* lk1 = (const float*)d_in[6];
    const float* lq2 = (const float*)d_in[7];
    const float* lk2 = (const float*)d_in[8];
    const float* rms = (const float*)d_in[9];

    float *pQ, *pK, *pV, *pOc;
    cudaGetSymbolAddress((void**)&pQ,  g_Q);
    cudaGetSymbolAddress((void**)&pK,  g_K);
    cudaGetSymbolAddress((void**)&pV,  g_V);
    cudaGetSymbolAddress((void**)&pOc, g_Oc);

    lambda_kernel<<<1, 512>>>(lq1, lk1, lq2, lk2);

    dim3 gqkv(48, MTOT/128);
    gemm_tf32<1><<<gqkv, 256>>>(X, Wq, Wk, Wv, pQ, pK, pV, DMODEL);

    cudaFuncSetAttribute(attn_kernel, cudaFuncAttributeMaxDynamicSharedMemorySize, ATTN_SMEM);
    attn_kernel<<<dim3(NN/64, BB*NUM_HEADS), 256, ATTN_SMEM>>>(rms);

    dim3 gout(DMODEL/128, MTOT/128);
    gemm_tf32<0><<<gout, 256>>>(pOc, Wo, nullptr, nullptr, (float*)d_out, nullptr, nullptr, D2);
}

// round 6
// speedup vs baseline: 2.9728x; 1.1470x over previous
#include <cuda_runtime.h>
#include <math.h>
#include <stdint.h>

#define NUM_HEADS 16
#define DHEAD 64
#define DE 128          // 2*DHEAD per head
#define DMODEL 1024
#define D2 2048
#define BB 4
#define NN 1024
#define MTOT (BB*NN)    // 4096
#define QKP 132         // smem pitch for Q/K tiles (132 mod 32 = 4 -> bijective frag banks)
#define VP  136         // smem pitch for V tile (136 mod 32 = 8 -> bijective B-frag banks)
#define PP  68          // smem pitch for P tiles (68 mod 32 = 4 -> bijective A-frag banks)
#define GP 36           // smem pitch for GEMM tiles

// Scratch (device globals; allocation APIs are forbidden)
__device__ float g_Q[(size_t)BB*NUM_HEADS*NN*DE];
__device__ float g_K[(size_t)BB*NUM_HEADS*NN*DE];
__device__ float g_V[(size_t)BB*NUM_HEADS*NN*DE];
__device__ float g_Oc[(size_t)BB*NN*D2];
__device__ float g_lam[NUM_HEADS];

__device__ __forceinline__ uint32_t f2tf(float f) {
    uint32_t u;
    asm("cvt.rna.tf32.f32 %0, %1;" : "=r"(u) : "f"(f));
    return u;
}

__device__ __forceinline__ void mma_tf32(float* d, const uint32_t* a, const uint32_t* b) {
    asm volatile(
        "mma.sync.aligned.m16n8k8.row.col.f32.tf32.tf32.f32 "
        "{%0,%1,%2,%3}, {%4,%5,%6,%7}, {%8,%9}, {%0,%1,%2,%3};"
        : "+f"(d[0]), "+f"(d[1]), "+f"(d[2]), "+f"(d[3])
        : "r"(a[0]), "r"(a[1]), "r"(a[2]), "r"(a[3]), "r"(b[0]), "r"(b[1]));
}

// ---------------------------------------------------------------------------
// lambda[h]
// ---------------------------------------------------------------------------
__global__ void lambda_kernel(const float* __restrict__ lq1, const float* __restrict__ lk1,
                              const float* __restrict__ lq2, const float* __restrict__ lk2) {
    int w = threadIdx.x >> 5, lane = threadIdx.x & 31;
    int base = w * 64;
    float s1 = lq1[base+lane]*lk1[base+lane] + lq1[base+32+lane]*lk1[base+32+lane];
    float s2 = lq2[base+lane]*lk2[base+lane] + lq2[base+32+lane]*lk2[base+32+lane];
    #pragma unroll
    for (int off = 16; off; off >>= 1) {
        s1 += __shfl_xor_sync(0xffffffffu, s1, off);
        s2 += __shfl_xor_sync(0xffffffffu, s2, off);
    }
    if (lane == 0) g_lam[w] = expf(s1) - expf(s2) + 0.8f;
}

// ---------------------------------------------------------------------------
// tf32 tensor-core GEMM (unchanged, proven): C = A @ W^T (NT)
// ---------------------------------------------------------------------------
template<int MODE>
__global__ __launch_bounds__(256, 2) void gemm_tf32(
    const float* __restrict__ A,
    const float* __restrict__ B0, const float* __restrict__ B1, const float* __restrict__ B2,
    float* __restrict__ C0, float* __restrict__ C1, float* __restrict__ C2,
    int K)
{
    __shared__ float As[128][GP];
    __shared__ float Bs[128][GP];

    int t = threadIdx.x;
    int wid = t >> 5, lane = t & 31;
    int row0 = blockIdx.y * 128;

    const float* Bm;
    float* C;
    int col0;
    if (MODE == 1) {
        int which = blockIdx.x >> 4;
        col0 = (blockIdx.x & 15) * 128;
        Bm = (which == 0) ? B0 : ((which == 1) ? B1 : B2);
        C  = (which == 0) ? C0 : ((which == 1) ? C1 : C2);
    } else {
        col0 = blockIdx.x * 128;
        Bm = B0; C = C0;
    }

    int r0 = t >> 3;
    int kq = (t & 7) * 4;
    const float* Ag = A  + (size_t)(row0 + r0) * K + kq;
    const float* Bg = Bm + (size_t)(col0 + r0) * K + kq;

    float4 ar[4], br[4];
    #pragma unroll
    for (int l = 0; l < 4; l++) {
        ar[l] = *(const float4*)(Ag + (size_t)l * 32 * K);
        br[l] = *(const float4*)(Bg + (size_t)l * 32 * K);
    }

    float acc[4][4][4];
    #pragma unroll
    for (int i = 0; i < 4; i++)
        #pragma unroll
        for (int j = 0; j < 4; j++)
            #pragma unroll
            for (int r = 0; r < 4; r++) acc[i][j][r] = 0.f;

    int wm = (wid & 1) * 64;
    int wn = (wid >> 1) * 32;
    int fr = lane >> 2;
    int fc = lane & 3;

    for (int k0 = 0; k0 < K; k0 += 32) {
        #pragma unroll
        for (int l = 0; l < 4; l++) {
            uint4 ua = make_uint4(f2tf(ar[l].x), f2tf(ar[l].y), f2tf(ar[l].z), f2tf(ar[l].w));
            *(uint4*)&As[r0 + l*32][kq] = ua;
            uint4 ub = make_uint4(f2tf(br[l].x), f2tf(br[l].y), f2tf(br[l].z), f2tf(br[l].w));
            *(uint4*)&Bs[r0 + l*32][kq] = ub;
        }
        __syncthreads();

        if (k0 + 32 < K) {
            #pragma unroll
            for (int l = 0; l < 4; l++) {
                ar[l] = *(const float4*)(Ag + (size_t)l * 32 * K + k0 + 32);
                br[l] = *(const float4*)(Bg + (size_t)l * 32 * K + k0 + 32);
            }
        }

        #pragma unroll
        for (int kc = 0; kc < 32; kc += 8) {
            uint32_t af[4][4], bf[4][2];
            #pragma unroll
            for (int i = 0; i < 4; i++) {
                af[i][0] = __float_as_uint(As[wm + i*16 +     fr][kc +     fc]);
                af[i][1] = __float_as_uint(As[wm + i*16 + 8 + fr][kc +     fc]);
                af[i][2] = __float_as_uint(As[wm + i*16 +     fr][kc + 4 + fc]);
                af[i][3] = __float_as_uint(As[wm + i*16 + 8 + fr][kc + 4 + fc]);
            }
            #pragma unroll
            for (int j = 0; j < 4; j++) {
                bf[j][0] = __float_as_uint(Bs[wn + j*8 + fr][kc +     fc]);
                bf[j][1] = __float_as_uint(Bs[wn + j*8 + fr][kc + 4 + fc]);
            }
            #pragma unroll
            for (int i = 0; i < 4; i++)
                #pragma unroll
                for (int j = 0; j < 4; j++)
                    mma_tf32(acc[i][j], af[i], bf[j]);
        }
        __syncthreads();
    }

    #pragma unroll
    for (int i = 0; i < 4; i++) {
        int rr = row0 + wm + i*16 + fr;
        #pragma unroll
        for (int j = 0; j < 4; j++) {
            int cc = col0 + wn + j*8 + fc*2;
            float2 v0 = make_float2(acc[i][j][0], acc[i][j][1]);
            float2 v1 = make_float2(acc[i][j][2], acc[i][j][3]);
            if (MODE == 0) {
                *(float2*)(C + (size_t)rr * DMODEL + cc) = v0;
                *(float2*)(C + (size_t)(rr + 8) * DMODEL + cc) = v1;
            } else {
                int h = cc >> 7, e = cc & 127;
                int bb = rr >> 10, n = rr & 1023;
                *(float2*)(C + (((size_t)(bb*NUM_HEADS + h) * NN + n) * DE + e)) = v0;
                int rr2 = rr + 8;
                bb = rr2 >> 10; n = rr2 & 1023;
                *(float2*)(C + (((size_t)(bb*NUM_HEADS + h) * NN + n) * DE + e)) = v1;
            }
        }
    }
}

// ---------------------------------------------------------------------------
// Fully-tensorized dual-stream flash attention:
//  - logits via 3xTF32 compensated mma (fp32-accurate)
//  - P@V via tf32 mma
//  - lambda-combine + RMS norm epilogue
// Grid: (N/64, B*H). 256 threads = 8 warps.
// Warp w: rows rt=(w>>1)*16 .. +15; score col-half ch=(w&1)*32; PV col-half nh=(w&1)*64.
// ---------------------------------------------------------------------------
__global__ __launch_bounds__(256) void attn_kernel(const float* __restrict__ rms_scale) {
    extern __shared__ float sm[];
    float* Qh  = sm;                       // 64 x QKP (tf32 hi)
    float* Ql  = Qh + 64*QKP;              // 64 x QKP (tf32 lo)
    float* Kh  = Ql + 64*QKP;
    float* Kl  = Kh + 64*QKP;
    float* Vs  = Kl + 64*QKP;              // 64 x VP (tf32)
    float* P1  = Vs + 64*VP;               // 64 x PP (tf32)
    float* P2  = P1 + 64*PP;
    float* bm1 = P2 + 64*PP;               // [2][64] row-max exchange, stream1
    float* bm2 = bm1 + 128;
    float* bs1 = bm2 + 128;                // [2][64] row-sum exchange
    float* bs2 = bs1 + 128;

    int t  = threadIdx.x;
    int bh = blockIdx.y;
    int h  = bh & (NUM_HEADS - 1);
    int b  = bh >> 4;
    int qb = blockIdx.x * 64;
    const float* Qp = g_Q + (size_t)bh * NN * DE;
    const float* Kp = g_K + (size_t)bh * NN * DE;
    const float* Vp = g_V + (size_t)bh * NN * DE;

    int lane = t & 31, wid = t >> 5;
    int gid = lane >> 2, tig = lane & 3;
    int rt = (wid >> 1) * 16;
    int half = wid & 1;
    int ch = half * 32;     // score col-half
    int nh = half * 64;     // PV col-half
    int rA = rt + gid, rB = rt + gid + 8;

    // load Q tile (64x128), split hi/lo
    #pragma unroll
    for (int l = 0; l < 8; l++) {
        int c = t + l*256;
        int r = c >> 5, dq = (c & 31) * 4;
        float4 q = *(const float4*)(Qp + (size_t)(qb + r)*DE + dq);
        uint4 hi = make_uint4(f2tf(q.x), f2tf(q.y), f2tf(q.z), f2tf(q.w));
        uint4 lo = make_uint4(f2tf(q.x - __uint_as_float(hi.x)),
                              f2tf(q.y - __uint_as_float(hi.y)),
                              f2tf(q.z - __uint_as_float(hi.z)),
                              f2tf(q.w - __uint_as_float(hi.w)));
        *(uint4*)&Qh[r*QKP + dq] = hi;
        *(uint4*)&Ql[r*QKP + dq] = lo;
    }

    float m1a = -1e30f, m1b = -1e30f, m2a = -1e30f, m2b = -1e30f;
    float l1a = 0.f, l1b = 0.f, l2a = 0.f, l2b = 0.f;
    float o1[8][4], o2[8][4];
    #pragma unroll
    for (int f = 0; f < 8; f++)
        #pragma unroll
        for (int r = 0; r < 4; r++) { o1[f][r] = 0.f; o2[f][r] = 0.f; }

    float lam = g_lam[h];

    int nkb = blockIdx.x + 1;   // causal: key blocks 0..blockIdx.x
    for (int jb = 0; jb < nkb; jb++) {
        int kb = jb * 64;
        // load K (split hi/lo) and V (tf32) tiles
        #pragma unroll
        for (int l = 0; l < 8; l++) {
            int c = t + l*256;
            int r = c >> 5, dq = (c & 31) * 4;
            float4 kq = *(const float4*)(Kp + (size_t)(kb + r)*DE + dq);
            uint4 hi = make_uint4(f2tf(kq.x), f2tf(kq.y), f2tf(kq.z), f2tf(kq.w));
            uint4 lo = make_uint4(f2tf(kq.x - __uint_as_float(hi.x)),
                                  f2tf(kq.y - __uint_as_float(hi.y)),
                                  f2tf(kq.z - __uint_as_float(hi.z)),
                                  f2tf(kq.w - __uint_as_float(hi.w)));
            *(uint4*)&Kh[r*QKP + dq] = hi;
            *(uint4*)&Kl[r*QKP + dq] = lo;
            float4 vv = *(const float4*)(Vp + (size_t)(kb + r)*DE + dq);
            uint4 uv = make_uint4(f2tf(vv.x), f2tf(vv.y), f2tf(vv.z), f2tf(vv.w));
            *(uint4*)&Vs[r*VP + dq] = uv;
        }
        __syncthreads();

        // ---- logits via 3xTF32 mma ----
        float s1[4][4], s2[4][4];
        #pragma unroll
        for (int i = 0; i < 4; i++)
            #pragma unroll
            for (int j = 0; j < 4; j++) { s1[i][j] = 0.f; s2[i][j] = 0.f; }

        #pragma unroll
        for (int kc = 0; kc < 64; kc += 8) {
            uint32_t a1h[4], a1l[4], a2h[4], a2l[4];
            a1h[0] = __float_as_uint(Qh[rA*QKP + kc + tig]);
            a1h[1] = __float_as_uint(Qh[rB*QKP + kc + tig]);
            a1h[2] = __float_as_uint(Qh[rA*QKP + kc + tig + 4]);
            a1h[3] = __float_as_uint(Qh[rB*QKP + kc + tig + 4]);
            a1l[0] = __float_as_uint(Ql[rA*QKP + kc + tig]);
            a1l[1] = __float_as_uint(Ql[rB*QKP + kc + tig]);
            a1l[2] = __float_as_uint(Ql[rA*QKP + kc + tig + 4]);
            a1l[3] = __float_as_uint(Ql[rB*QKP + kc + tig + 4]);
            a2h[0] = __float_as_uint(Qh[rA*QKP + 64 + kc + tig]);
            a2h[1] = __float_as_uint(Qh[rB*QKP + 64 + kc + tig]);
            a2h[2] = __float_as_uint(Qh[rA*QKP + 64 + kc + tig + 4]);
            a2h[3] = __float_as_uint(Qh[rB*QKP + 64 + kc + tig + 4]);
            a2l[0] = __float_as_uint(Ql[rA*QKP + 64 + kc + tig]);
            a2l[1] = __float_as_uint(Ql[rB*QKP + 64 + kc + tig]);
            a2l[2] = __float_as_uint(Ql[rA*QKP + 64 + kc + tig + 4]);
            a2l[3] = __float_as_uint(Ql[rB*QKP + 64 + kc + tig + 4]);
            #pragma unroll
            for (int nt = 0; nt < 4; nt++) {
                int n0 = ch + nt*8 + gid;
                uint32_t b1h[2], b1l[2], b2h[2], b2l[2];
                b1h[0] = __float_as_uint(Kh[n0*QKP + kc + tig]);
                b1h[1] = __float_as_uint(Kh[n0*QKP + kc + tig + 4]);
                b1l[0] = __float_as_uint(Kl[n0*QKP + kc + tig]);
                b1l[1] = __float_as_uint(Kl[n0*QKP + kc + tig + 4]);
                b2h[0] = __float_as_uint(Kh[n0*QKP + 64 + kc + tig]);
                b2h[1] = __float_as_uint(Kh[n0*QKP + 64 + kc + tig + 4]);
                b2l[0] = __float_as_uint(Kl[n0*QKP + 64 + kc + tig]);
                b2l[1] = __float_as_uint(Kl[n0*QKP + 64 + kc + tig + 4]);
                mma_tf32(s1[nt], a1h, b1h);
                mma_tf32(s1[nt], a1l, b1h);
                mma_tf32(s1[nt], a1h, b1l);
                mma_tf32(s2[nt], a2h, b2h);
                mma_tf32(s2[nt], a2l, b2h);
                mma_tf32(s2[nt], a2h, b2l);
            }
        }

        // ---- scale (+ diagonal mask) ----
        bool last = (jb == nkb - 1);
        #pragma unroll
        for (int nt = 0; nt < 4; nt++)
            #pragma unroll
            for (int c = 0; c < 4; c++) {
                float v1 = s1[nt][c] * 0.125f;
                float v2 = s2[nt][c] * 0.125f;
                if (last) {
                    int col = ch + nt*8 + 2*tig + (c & 1);
                    int row = rt + gid + ((c & 2) ? 8 : 0);
                    if (col > row) { v1 = -1e30f; v2 = -1e30f; }
                }
                s1[nt][c] = v1; s2[nt][c] = v2;
            }

        // ---- row max (own 32 cols -> cross-half exchange) ----
        float mt1a = -1e30f, mt1b = -1e30f, mt2a = -1e30f, mt2b = -1e30f;
        #pragma unroll
        for (int nt = 0; nt < 4; nt++) {
            mt1a = fmaxf(mt1a, fmaxf(s1[nt][0], s1[nt][1]));
            mt1b = fmaxf(mt1b, fmaxf(s1[nt][2], s1[nt][3]));
            mt2a = fmaxf(mt2a, fmaxf(s2[nt][0], s2[nt][1]));
            mt2b = fmaxf(mt2b, fmaxf(s2[nt][2], s2[nt][3]));
        }
        #pragma unroll
        for (int off = 1; off <= 2; off <<= 1) {
            mt1a = fmaxf(mt1a, __shfl_xor_sync(0xffffffffu, mt1a, off));
            mt1b = fmaxf(mt1b, __shfl_xor_sync(0xffffffffu, mt1b, off));
            mt2a = fmaxf(mt2a, __shfl_xor_sync(0xffffffffu, mt2a, off));
            mt2b = fmaxf(mt2b, __shfl_xor_sync(0xffffffffu, mt2b, off));
        }
        if (tig == 0) {
            bm1[half*64 + rA] = mt1a; bm1[half*64 + rB] = mt1b;
            bm2[half*64 + rA] = mt2a; bm2[half*64 + rB] = mt2b;
        }
        __syncthreads();
        float M1a = fmaxf(m1a, fmaxf(bm1[rA], bm1[64 + rA]));
        float M1b = fmaxf(m1b, fmaxf(bm1[rB], bm1[64 + rB]));
        float M2a = fmaxf(m2a, fmaxf(bm2[rA], bm2[64 + rA]));
        float M2b = fmaxf(m2b, fmaxf(bm2[rB], bm2[64 + rB]));
        float c1a = __expf(m1a - M1a), c1b = __expf(m1b - M1b);
        float c2a = __expf(m2a - M2a), c2b = __expf(m2b - M2b);
        m1a = M1a; m1b = M1b; m2a = M2a; m2b = M2b;

        // ---- exp, write tf32 P, partial sums ----
        float ps1a = 0.f, ps1b = 0.f, ps2a = 0.f, ps2b = 0.f;
        #pragma unroll
        for (int nt = 0; nt < 4; nt++) {
            int colb = ch + nt*8 + 2*tig;
            float p0 = __uint_as_float(f2tf(__expf(s1[nt][0] - M1a)));
            float p1 = __uint_as_float(f2tf(__expf(s1[nt][1] - M1a)));
            float p2 = __uint_as_float(f2tf(__expf(s1[nt][2] - M1b)));
            float p3 = __uint_as_float(f2tf(__expf(s1[nt][3] - M1b)));
            ps1a += p0 + p1; ps1b += p2 + p3;
            *(float2*)&P1[rA*PP + colb] = make_float2(p0, p1);
            *(float2*)&P1[rB*PP + colb] = make_float2(p2, p3);
            float q0 = __uint_as_float(f2tf(__expf(s2[nt][0] - M2a)));
            float q1 = __uint_as_float(f2tf(__expf(s2[nt][1] - M2a)));
            float q2 = __uint_as_float(f2tf(__expf(s2[nt][2] - M2b)));
            float q3 = __uint_as_float(f2tf(__expf(s2[nt][3] - M2b)));
            ps2a += q0 + q1; ps2b += q2 + q3;
            *(float2*)&P2[rA*PP + colb] = make_float2(q0, q1);
            *(float2*)&P2[rB*PP + colb] = make_float2(q2, q3);
        }
        #pragma unroll
        for (int off = 1; off <= 2; off <<= 1) {
            ps1a += __shfl_xor_sync(0xffffffffu, ps1a, off);
            ps1b += __shfl_xor_sync(0xffffffffu, ps1b, off);
            ps2a += __shfl_xor_sync(0xffffffffu, ps2a, off);
            ps2b += __shfl_xor_sync(0xffffffffu, ps2b, off);
        }
        if (tig == 0) {
            bs1[half*64 + rA] = ps1a; bs1[half*64 + rB] = ps1b;
            bs2[half*64 + rA] = ps2a; bs2[half*64 + rB] = ps2b;
        }
        __syncthreads();
        l1a = l1a*c1a + bs1[rA] + bs1[64 + rA];
        l1b = l1b*c1b + bs1[rB] + bs1[64 + rB];
        l2a = l2a*c2a + bs2[rA] + bs2[64 + rA];
        l2b = l2b*c2b + bs2[rB] + bs2[64 + rB];

        // ---- P @ V on tensor cores ----
        #pragma unroll
        for (int f = 0; f < 8; f++) {
            o1[f][0] *= c1a; o1[f][1] *= c1a; o1[f][2] *= c1b; o1[f][3] *= c1b;
            o2[f][0] *= c2a; o2[f][1] *= c2a; o2[f][2] *= c2b; o2[f][3] *= c2b;
        }
        #pragma unroll
        for (int kc = 0; kc < 64; kc += 8) {
            uint32_t a1f[4], a2f[4];
            a1f[0] = __float_as_uint(P1[rA*PP + kc + tig]);
            a1f[1] = __float_as_uint(P1[rB*PP + kc + tig]);
            a1f[2] = __float_as_uint(P1[rA*PP + kc + tig + 4]);
            a1f[3] = __float_as_uint(P1[rB*PP + kc + tig + 4]);
            a2f[0] = __float_as_uint(P2[rA*PP + kc + tig]);
            a2f[1] = __float_as_uint(P2[rB*PP + kc + tig]);
            a2f[2] = __float_as_uint(P2[rA*PP + kc + tig + 4]);
            a2f[3] = __float_as_uint(P2[rB*PP + kc + tig + 4]);
            #pragma unroll
            for (int f = 0; f < 8; f++) {
                uint32_t bf[2];
                bf[0] = __float_as_uint(Vs[(kc + tig    )*VP + nh + f*8 + gid]);
                bf[1] = __float_as_uint(Vs[(kc + tig + 4)*VP + nh + f*8 + gid]);
                mma_tf32(o1[f], a1f, bf);
                mma_tf32(o2[f], a2f, bf);
            }
        }
        __syncthreads();
    }

    // ---- finalize: combine, RMS-norm, write Oc ----
    float il1a = 1.0f / l1a, il1b = 1.0f / l1b;
    float il2a = 1.0f / l2a, il2b = 1.0f / l2b;

    float ssA = 0.f, ssB = 0.f;
    #pragma unroll
    for (int f = 0; f < 8; f++) {
        o1[f][0] = o1[f][0]*il1a - lam*o2[f][0]*il2a;
        o1[f][1] = o1[f][1]*il1a - lam*o2[f][1]*il2a;
        o1[f][2] = o1[f][2]*il1b - lam*o2[f][2]*il2b;
        o1[f][3] = o1[f][3]*il1b - lam*o2[f][3]*il2b;
        ssA += o1[f][0]*o1[f][0] + o1[f][1]*o1[f][1];
        ssB += o1[f][2]*o1[f][2] + o1[f][3]*o1[f][3];
    }
    ssA += __shfl_xor_sync(0xffffffffu, ssA, 1);
    ssA += __shfl_xor_sync(0xffffffffu, ssA, 2);
    ssB += __shfl_xor_sync(0xffffffffu, ssB, 1);
    ssB += __shfl_xor_sync(0xffffffffu, ssB, 2);

    // cross-half reduction via bm1/bm2 (free after loop)
    if (tig == 0) {
        float* dst = half ? bm2 : bm1;
        dst[rA] = ssA;
        dst[rB] = ssB;
    }
    __syncthreads();
    float totA = bm1[rA] + bm2[rA];
    float totB = bm1[rB] + bm2[rB];
    float scA = rsqrtf(totA * (1.0f/128.0f) + 1e-5f) * 0.2f;
    float scB = rsqrtf(totB * (1.0f/128.0f) + 1e-5f) * 0.2f;

    size_t obaseA = ((size_t)b * NN + qb + rA) * D2 + h * DE;
    size_t obaseB = ((size_t)b * NN + qb + rB) * D2 + h * DE;
    #pragma unroll
    for (int f = 0; f < 8; f++) {
        int col = nh + f*8 + 2*tig;
        float2 rs = *(const float2*)(rms_scale + col);
        *(float2*)(g_Oc + obaseA + col) = make_float2(o1[f][0]*scA*rs.x, o1[f][1]*scA*rs.y);
        *(float2*)(g_Oc + obaseB + col) = make_float2(o1[f][2]*scB*rs.x, o1[f][3]*scB*rs.y);
    }
}

// ---------------------------------------------------------------------------
// Host launcher
// ---------------------------------------------------------------------------
#define ATTN_SMEM ((4*64*QKP + 64*VP + 2*64*PP + 4*128) * 4)   // 206848 bytes

extern "C" void kernel_launch(void* const* d_in, const int* in_sizes, int n_in,
                              void* d_out, int out_size) {
    const float* X   = (const float*)d_in[0];
    const float* Wq  = (const float*)d_in[1];
    const float* Wk  = (const float*)d_in[2];
    const float* Wv  = (const float*)d_in[3];
    const float* Wo  = (const float*)d_in[4];
    const float* lq1 = (const float*)d_in[5];
    const float* lk1 = (const float*)d_in[6];
    const float* lq2 = (const float*)d_in[7];
    const float* lk2 = (const float*)d_in[8];
    const float* rms = (const float*)d_in[9];

    float *pQ, *pK, *pV, *pOc;
    cudaGetSymbolAddress((void**)&pQ,  g_Q);
    cudaGetSymbolAddress((void**)&pK,  g_K);
    cudaGetSymbolAddress((void**)&pV,  g_V);
    cudaGetSymbolAddress((void**)&pOc, g_Oc);

    lambda_kernel<<<1, 512>>>(lq1, lk1, lq2, lk2);

    dim3 gqkv(48, MTOT/128);
    gemm_tf32<1><<<gqkv, 256>>>(X, Wq, Wk, Wv, pQ, pK, pV, DMODEL);

    cudaFuncSetAttribute(attn_kernel, cudaFuncAttributeMaxDynamicSharedMemorySize, ATTN_SMEM);
    attn_kernel<<<dim3(NN/64, BB*NUM_HEADS), 256, ATTN_SMEM>>>(rms);

    dim3 gout(DMODEL/128, MTOT/128);
    gemm_tf32<0><<<gout, 256>>>(pOc, Wo, nullptr, nullptr, (float*)d_out, nullptr, nullptr, D2);
}